// round 5
// baseline (speedup 1.0000x reference)
#include <cuda_runtime.h>
#include <cuda_bf16.h>
#include <cstdint>
#include <math.h>

#define EN_MAX 200000
#define TN_MAX 600000
#define HH 128
#define IC 64
#define BSZ 8
#define NRAD 6
#define SBFK 42
#define TK 294

// ---------------- scratch (device globals; no allocations) ----------------
__device__ float g_xji[EN_MAX * HH];
__device__ float g_rbfh[EN_MAX * HH];
__device__ float g_rbfh2[EN_MAX * HH];
__device__ float g_rb8[EN_MAX * BSZ];
__device__ float g_xdown[EN_MAX * IC];
__device__ float g_acc[EN_MAX * IC];
__device__ float g_t8[TN_MAX * BSZ];
__device__ float g_s8[TN_MAX * BSZ];
__device__ float g_bufA[EN_MAX * HH];
__device__ float g_bufB[EN_MAX * HH];
__device__ float g_bufC[EN_MAX * HH];
// transposed+split weights: 11 slots of up to 128x128
__device__ __nv_bfloat16 g_whi[11 * HH * HH];
__device__ __nv_bfloat16 g_wlo[11 * HH * HH];

__device__ __forceinline__ float silu_f(float x) {
    return x / (1.0f + __expf(-x));
}

__device__ __forceinline__ uint32_t smem_to_u32(const void* p) {
    uint32_t a;
    asm("{ .reg .u64 t; cvta.to.shared.u64 t, %1; cvt.u32.u64 %0, t; }" : "=r"(a) : "l"(p));
    return a;
}
__device__ __forceinline__ uint32_t b2u(__nv_bfloat162 v) {
    return *reinterpret_cast<uint32_t*>(&v);
}
__device__ __forceinline__ void ldsm4(uint32_t* r, uint32_t addr) {
    asm volatile("ldmatrix.sync.aligned.m8n8.x4.shared.b16 {%0,%1,%2,%3}, [%4];"
                 : "=r"(r[0]), "=r"(r[1]), "=r"(r[2]), "=r"(r[3]) : "r"(addr));
}
__device__ __forceinline__ void mma16816(float* c, const uint32_t* a, const uint32_t* b) {
    asm volatile("mma.sync.aligned.m16n8k16.row.col.f32.bf16.bf16.f32 "
                 "{%0,%1,%2,%3}, {%4,%5,%6,%7}, {%8,%9}, {%0,%1,%2,%3};"
                 : "+f"(c[0]), "+f"(c[1]), "+f"(c[2]), "+f"(c[3])
                 : "r"(a[0]), "r"(a[1]), "r"(a[2]), "r"(a[3]), "r"(b[0]), "r"(b[1]));
}

// -------- weight prep: W[K,N] f32 -> transposed [N,K] bf16 hi/lo ----------
__global__ void wprep_kernel(const float* __restrict__ W,
                             __nv_bfloat16* __restrict__ hi,
                             __nv_bfloat16* __restrict__ lo, int K, int N)
{
    const int i = blockIdx.x * blockDim.x + threadIdx.x;
    if (i >= K * N) return;
    const int n = i / K, k = i % K;
    const float x = W[(size_t)k * N + n];
    const __nv_bfloat16 h = __float2bfloat16(x);
    hi[(size_t)n * K + k] = h;
    lo[(size_t)n * K + k] = __float2bfloat16(x - __bfloat162float(h));
}

// ------------- mma.sync bf16-split GEMM + fused epilogue ------------------
// out[row,j] = epi( sum_k in[row,k] * W[k,j] ); W prepped as Bhi/Blo [N,K].
// CTA: 128 x NOUT tile, 8 warps (4 x 2), full K resident, hi/lo 3-MMA split.
template <int KIN, int NOUT>
__global__ void __launch_bounds__(256, 1)
gemm_mma(const float* __restrict__ in,
         const __nv_bfloat16* __restrict__ Bhi,
         const __nv_bfloat16* __restrict__ Blo,
         const float* __restrict__ bias,
         const float* __restrict__ mulv,
         const float* __restrict__ addv,
         float* __restrict__ out,
         const float* __restrict__ mul2,
         float* __restrict__ out2,
         int nrows, int act)
{
    constexpr int PITCH = KIN * 2;          // bytes per bf16 row
    constexpr int ASZ = 128 * PITCH;        // bytes per A buffer
    constexpr int BSZB = NOUT * PITCH;      // bytes per B buffer
    constexpr int NF = NOUT / 16;           // n-frags per warp (8 or 4)
    constexpr int CPR = KIN / 8;            // 16B chunks per row

    extern __shared__ char smem[];
    char* As_hi = smem;
    char* As_lo = smem + ASZ;
    char* Bs_hi = smem + 2 * ASZ;
    char* Bs_lo = smem + 2 * ASZ + BSZB;
    const uint32_t sb = smem_to_u32(smem);
    const uint32_t a_hi_u = sb, b_hi_u = sb + 2 * ASZ;

    const int tid = threadIdx.x, wid = tid >> 5, lane = tid & 31;
    const int r0 = blockIdx.x * 128;

    // ---- stage A: f32 -> bf16 hi/lo, swizzled ----
    for (int task = tid; task < 128 * CPR; task += 256) {
        const int row = task / CPR, ch = task % CPR;
        int gr = r0 + row;
        if (gr >= nrows) gr = nrows - 1;
        const float4 v0 = *reinterpret_cast<const float4*>(in + (size_t)gr * KIN + ch * 8);
        const float4 v1 = *reinterpret_cast<const float4*>(in + (size_t)gr * KIN + ch * 8 + 4);
        const __nv_bfloat162 h0 = __floats2bfloat162_rn(v0.x, v0.y);
        const __nv_bfloat162 h1 = __floats2bfloat162_rn(v0.z, v0.w);
        const __nv_bfloat162 h2 = __floats2bfloat162_rn(v1.x, v1.y);
        const __nv_bfloat162 h3 = __floats2bfloat162_rn(v1.z, v1.w);
        const float2 f0 = __bfloat1622float2(h0), f1 = __bfloat1622float2(h1);
        const float2 f2 = __bfloat1622float2(h2), f3 = __bfloat1622float2(h3);
        const __nv_bfloat162 l0 = __floats2bfloat162_rn(v0.x - f0.x, v0.y - f0.y);
        const __nv_bfloat162 l1 = __floats2bfloat162_rn(v0.z - f1.x, v0.w - f1.y);
        const __nv_bfloat162 l2 = __floats2bfloat162_rn(v1.x - f2.x, v1.y - f2.y);
        const __nv_bfloat162 l3 = __floats2bfloat162_rn(v1.z - f3.x, v1.w - f3.y);
        const uint32_t off = row * PITCH + ((ch * 16) ^ ((row & 7) << 4));
        *reinterpret_cast<uint4*>(As_hi + off) = make_uint4(b2u(h0), b2u(h1), b2u(h2), b2u(h3));
        *reinterpret_cast<uint4*>(As_lo + off) = make_uint4(b2u(l0), b2u(l1), b2u(l2), b2u(l3));
    }
    // ---- stage B: prepped bf16 [N,K], swizzled ----
    for (int task = tid; task < NOUT * CPR; task += 256) {
        const int n = task / CPR, ch = task % CPR;
        const uint4 vh = *reinterpret_cast<const uint4*>(Bhi + (size_t)n * KIN + ch * 8);
        const uint4 vl = *reinterpret_cast<const uint4*>(Blo + (size_t)n * KIN + ch * 8);
        const uint32_t off = n * PITCH + ((ch * 16) ^ ((n & 7) << 4));
        *reinterpret_cast<uint4*>(Bs_hi + off) = vh;
        *reinterpret_cast<uint4*>(Bs_lo + off) = vl;
    }
    __syncthreads();

    const int warp_m = wid & 3, warp_n = wid >> 2;
    const int mo = warp_m * 32;
    const int no = warp_n * (NOUT / 2);

    float acc[2][NF][4];
    #pragma unroll
    for (int mi = 0; mi < 2; ++mi)
        #pragma unroll
        for (int f = 0; f < NF; ++f)
            #pragma unroll
            for (int q = 0; q < 4; ++q) acc[mi][f][q] = 0.f;

    // ldmatrix per-lane decomposition (x4: lane/8 = matrix, lane%8 = row)
    const int jm = lane >> 3, rr = lane & 7;
    const int row_off = (jm & 1) * 8 + rr;    // matrix row offset
    const int koff = (jm >> 1) * 8;           // matrix k offset

    #pragma unroll
    for (int k0 = 0; k0 < KIN; k0 += 16) {
        const uint32_t colb = (uint32_t)(k0 + koff) * 2;
        uint32_t ah[2][4], al[2][4];
        #pragma unroll
        for (int mi = 0; mi < 2; ++mi) {
            const int row = mo + mi * 16 + row_off;
            const uint32_t ad = a_hi_u + row * PITCH + (colb ^ ((row & 7) << 4));
            ldsm4(ah[mi], ad);
            ldsm4(al[mi], ad + ASZ);
        }
        uint32_t bh[NF][2], bl[NF][2];
        #pragma unroll
        for (int g = 0; g < NF / 2; ++g) {
            const int n = no + g * 16 + row_off;
            const uint32_t bd = b_hi_u + n * PITCH + (colb ^ ((n & 7) << 4));
            uint32_t t[4];
            ldsm4(t, bd);
            bh[2 * g][0] = t[0]; bh[2 * g][1] = t[2];
            bh[2 * g + 1][0] = t[1]; bh[2 * g + 1][1] = t[3];
            ldsm4(t, bd + BSZB);
            bl[2 * g][0] = t[0]; bl[2 * g][1] = t[2];
            bl[2 * g + 1][0] = t[1]; bl[2 * g + 1][1] = t[3];
        }
        #pragma unroll
        for (int mi = 0; mi < 2; ++mi)
            #pragma unroll
            for (int f = 0; f < NF; ++f) {
                mma16816(acc[mi][f], ah[mi], bh[f]);
                mma16816(acc[mi][f], al[mi], bh[f]);
                mma16816(acc[mi][f], ah[mi], bl[f]);
            }
    }

    // ---- epilogue ----
    const int tr4 = lane >> 2, tc2 = (lane & 3) * 2;
    #pragma unroll
    for (int mi = 0; mi < 2; ++mi) {
        #pragma unroll
        for (int h = 0; h < 2; ++h) {
            const int row = r0 + mo + mi * 16 + tr4 + h * 8;
            if (row < nrows) {
                #pragma unroll
                for (int f = 0; f < NF; ++f) {
                    const int col = no + f * 8 + tc2;
                    float v0 = acc[mi][f][h * 2 + 0];
                    float v1 = acc[mi][f][h * 2 + 1];
                    if (bias) { v0 += bias[col]; v1 += bias[col + 1]; }
                    if (act) { v0 = silu_f(v0); v1 = silu_f(v1); }
                    const size_t o = (size_t)row * NOUT + col;
                    if (mulv) {
                        const float2 m = *reinterpret_cast<const float2*>(mulv + o);
                        v0 *= m.x; v1 *= m.y;
                    }
                    if (addv) {
                        const float2 s = *reinterpret_cast<const float2*>(addv + o);
                        v0 += s.x; v1 += s.y;
                    }
                    *reinterpret_cast<float2*>(out + o) = make_float2(v0, v1);
                    if (out2) {
                        const float2 m = *reinterpret_cast<const float2*>(mul2 + o);
                        *reinterpret_cast<float2*>(out2 + o) = make_float2(v0 * m.x, v1 * m.y);
                    }
                }
            }
        }
    }
}

// ---------------- rbf basis helpers ----------------
__global__ void rb8_kernel(const float* __restrict__ rbf, const float* __restrict__ W1,
                           float* __restrict__ out, int n)
{
    const int e = blockIdx.x * blockDim.x + threadIdx.x;
    if (e >= n) return;
    float r[NRAD];
    #pragma unroll
    for (int i = 0; i < NRAD; ++i) r[i] = rbf[(size_t)e * NRAD + i];
    #pragma unroll
    for (int b = 0; b < BSZ; ++b) {
        float s = 0.f;
        #pragma unroll
        for (int i = 0; i < NRAD; ++i) s += r[i] * __ldg(&W1[i * BSZ + b]);
        out[(size_t)e * BSZ + b] = s;
    }
}

__global__ void rbfh_kernel(const float* __restrict__ rb8, const float* __restrict__ rbf,
                            const float* __restrict__ W_rbf2, const float* __restrict__ W_rbf,
                            float* __restrict__ rbfh, float* __restrict__ rbfh2, int n)
{
    __shared__ float w2[BSZ * HH];
    __shared__ float wr[NRAD * HH];
    const int j = threadIdx.x;
    #pragma unroll
    for (int b = 0; b < BSZ; ++b) w2[b * HH + j] = W_rbf2[b * HH + j];
    #pragma unroll
    for (int r = 0; r < NRAD; ++r) wr[r * HH + j] = W_rbf[r * HH + j];
    __syncthreads();

    const int row0 = blockIdx.x * 32;
    for (int rr = 0; rr < 32; ++rr) {
        const int row = row0 + rr;
        if (row >= n) return;
        const float4* rp = reinterpret_cast<const float4*>(rb8 + (size_t)row * BSZ);
        const float4 ra = __ldg(rp), rb = __ldg(rp + 1);
        float a1 = ra.x * w2[0 * HH + j] + ra.y * w2[1 * HH + j] +
                   ra.z * w2[2 * HH + j] + ra.w * w2[3 * HH + j] +
                   rb.x * w2[4 * HH + j] + rb.y * w2[5 * HH + j] +
                   rb.z * w2[6 * HH + j] + rb.w * w2[7 * HH + j];
        float a2 = 0.f;
        #pragma unroll
        for (int r = 0; r < NRAD; ++r) a2 += __ldg(&rbf[(size_t)row * NRAD + r]) * wr[r * HH + j];
        rbfh[(size_t)row * HH + j]  = a1;
        rbfh2[(size_t)row * HH + j] = a2;
    }
}

// ---------------- T-space: X[T,K] @ W1[K,8] -> out8[T,8] ----------------
template <int K, int PK>
__global__ void proj8_kernel(const float* __restrict__ X, const float* __restrict__ W1,
                             float* __restrict__ out8, int nrows)
{
    __shared__ float wcm[BSZ * PK];
    __shared__ float red[8][32 * 33];
    const int tid = threadIdx.x;
    for (int x = tid; x < BSZ * PK; x += blockDim.x) wcm[x] = 0.f;
    __syncthreads();
    for (int x = tid; x < K * BSZ; x += blockDim.x) {
        const int i = x / BSZ, b = x % BSZ;
        wcm[b * PK + i] = W1[x];
    }
    __syncthreads();

    const int warp = tid >> 5, lane = tid & 31;
    float* myred = &red[warp][0];
    const int nw = blockDim.x >> 5;
    constexpr int ITERS = (K + 31) / 32;

    for (int r0 = (blockIdx.x * nw + warp) * 4; r0 < nrows; r0 += gridDim.x * nw * 4) {
        float acc[4][BSZ] = {};
        const float* x0 = X + (size_t)r0 * K;
        #pragma unroll
        for (int k = 0; k < ITERS; ++k) {
            const int i = lane + k * 32;
            float xv[4] = {0.f, 0.f, 0.f, 0.f};
            if (i < K) {
                #pragma unroll
                for (int rr = 0; rr < 4; ++rr) xv[rr] = x0[(size_t)rr * K + i];
            }
            #pragma unroll
            for (int b = 0; b < BSZ; ++b) {
                const float w = wcm[b * PK + i];
                #pragma unroll
                for (int rr = 0; rr < 4; ++rr) acc[rr][b] += w * xv[rr];
            }
        }
        #pragma unroll
        for (int rr = 0; rr < 4; ++rr)
            #pragma unroll
            for (int b = 0; b < BSZ; ++b)
                myred[lane * 33 + rr * BSZ + b] = acc[rr][b];
        __syncwarp();
        float s = 0.f;
        #pragma unroll
        for (int l = 0; l < 32; ++l) s += myred[l * 33 + lane];
        out8[(size_t)r0 * BSZ + lane] = s;
        __syncwarp();
    }
}

// ---------------- triplet gather/scale/scatter ----------------
__global__ void triplet_kernel(const float* __restrict__ t8, const float* __restrict__ s8,
                               const float* __restrict__ W_t2, const float* __restrict__ W_sbf2,
                               const float* __restrict__ xdown,
                               const int* __restrict__ idx_kj, const int* __restrict__ idx_ji,
                               float* __restrict__ acc, int nt)
{
    __shared__ float wt2s[BSZ * IC];
    __shared__ float ws2s[BSZ * IC];
    const int tid = threadIdx.x;
    for (int i = tid; i < BSZ * IC; i += blockDim.x) { wt2s[i] = W_t2[i]; ws2s[i] = W_sbf2[i]; }
    __syncthreads();

    const int warp = tid >> 5, lane = tid & 31;
    const int total_warps = (blockDim.x * gridDim.x) >> 5;

    for (int tr = blockIdx.x * (blockDim.x >> 5) + warp; tr < nt; tr += total_warps) {
        const float4* tp = reinterpret_cast<const float4*>(t8 + (size_t)tr * BSZ);
        const float4 ta = __ldg(tp), tb = __ldg(tp + 1);
        const float4* sp = reinterpret_cast<const float4*>(s8 + (size_t)tr * BSZ);
        const float4 sa = __ldg(sp), sb = __ldg(sp + 1);
        const float tv[BSZ] = {ta.x, ta.y, ta.z, ta.w, tb.x, tb.y, tb.z, tb.w};
        const float sv[BSZ] = {sa.x, sa.y, sa.z, sa.w, sb.x, sb.y, sb.z, sb.w};
        const int kj = idx_kj[tr], ji = idx_ji[tr];
        const int c0 = lane, c1 = lane + 32;
        float t0 = 0.f, t1 = 0.f, s0 = 0.f, s1 = 0.f;
        #pragma unroll
        for (int b = 0; b < BSZ; ++b) {
            t0 += tv[b] * wt2s[b * IC + c0];
            t1 += tv[b] * wt2s[b * IC + c1];
            s0 += sv[b] * ws2s[b * IC + c0];
            s1 += sv[b] * ws2s[b * IC + c1];
        }
        const float g0 = xdown[(size_t)kj * IC + c0];
        const float g1 = xdown[(size_t)kj * IC + c1];
        atomicAdd(acc + (size_t)ji * IC + c0, g0 * t0 * s0);
        atomicAdd(acc + (size_t)ji * IC + c1, g1 * t1 * s1);
    }
}

__global__ void zero4_kernel(float4* __restrict__ p, int n4)
{
    const int i = blockIdx.x * blockDim.x + threadIdx.x;
    if (i < n4) p[i] = make_float4(0.f, 0.f, 0.f, 0.f);
}

// ---------------- launch ----------------
extern "C" void kernel_launch(void* const* d_in, const int* in_sizes, int n_in,
                              void* d_out, int out_size)
{
    const float* e1     = (const float*)d_in[0];
    const float* rbf    = (const float*)d_in[1];
    const float* sbf    = (const float*)d_in[2];
    const float* tt     = (const float*)d_in[3];
    const int*   idx_kj = (const int*)d_in[4];
    const int*   idx_ji = (const int*)d_in[5];
    const float* W_rbf1 = (const float*)d_in[6];
    const float* W_rbf2 = (const float*)d_in[7];
    const float* W_sbf1 = (const float*)d_in[8];
    const float* W_sbf2 = (const float*)d_in[9];
    const float* W_t1   = (const float*)d_in[10];
    const float* W_t2   = (const float*)d_in[11];
    const float* W_rbf  = (const float*)d_in[12];
    const float* W_kj   = (const float*)d_in[13];
    const float* b_kj   = (const float*)d_in[14];
    const float* W_ji   = (const float*)d_in[15];
    const float* b_ji   = (const float*)d_in[16];
    const float* W_down = (const float*)d_in[17];
    const float* W_up   = (const float*)d_in[18];
    const float* Wb1    = (const float*)d_in[19];
    const float* bb1    = (const float*)d_in[20];
    const float* Wb2    = (const float*)d_in[21];
    const float* bb2    = (const float*)d_in[22];
    const float* W_lin  = (const float*)d_in[23];
    const float* b_lin  = (const float*)d_in[24];
    const float* Wa1    = (const float*)d_in[25];
    const float* ba1    = (const float*)d_in[26];
    const float* Wa2    = (const float*)d_in[27];
    const float* ba2    = (const float*)d_in[28];

    const int E = in_sizes[0] / HH;
    const int T = in_sizes[4];

    float *xji, *rbfh, *rbfh2, *rb8, *xdown, *acc, *t8, *s8, *A, *B, *C;
    __nv_bfloat16 *whi, *wlo;
    cudaGetSymbolAddress((void**)&xji,   g_xji);
    cudaGetSymbolAddress((void**)&rbfh,  g_rbfh);
    cudaGetSymbolAddress((void**)&rbfh2, g_rbfh2);
    cudaGetSymbolAddress((void**)&rb8,   g_rb8);
    cudaGetSymbolAddress((void**)&xdown, g_xdown);
    cudaGetSymbolAddress((void**)&acc,   g_acc);
    cudaGetSymbolAddress((void**)&t8,    g_t8);
    cudaGetSymbolAddress((void**)&s8,    g_s8);
    cudaGetSymbolAddress((void**)&A,     g_bufA);
    cudaGetSymbolAddress((void**)&B,     g_bufB);
    cudaGetSymbolAddress((void**)&C,     g_bufC);
    cudaGetSymbolAddress((void**)&whi,   g_whi);
    cudaGetSymbolAddress((void**)&wlo,   g_wlo);

    float* out_e1 = (float*)d_out;
    float* out_e2 = (float*)d_out + (size_t)E * HH;

    // weight slots (transposed bf16 hi/lo), stride 128*128 elems
    const int WS = HH * HH;
    struct { const float* W; int K, N, slot; } wp[11] = {
        {W_ji, 128, 128, 0}, {W_kj, 128, 128, 1}, {W_down, 128, 64, 2}, {W_up, 64, 128, 3},
        {Wb1, 128, 128, 4}, {Wb2, 128, 128, 5}, {W_lin, 128, 128, 6},
        {Wa1, 128, 128, 7}, {Wa2, 128, 128, 8},
        {Wa1 + WS, 128, 128, 9}, {Wa2 + WS, 128, 128, 10}
    };
    for (int i = 0; i < 11; ++i)
        wprep_kernel<<<(wp[i].K * wp[i].N + 255) / 256, 256>>>(
            wp[i].W, whi + (size_t)wp[i].slot * WS, wlo + (size_t)wp[i].slot * WS, wp[i].K, wp[i].N);

    // dynamic smem: 2*A + 2*B bf16 buffers
    const int sm_hh = 2 * 128 * 256 + 2 * 128 * 256;  // 131072
    const int sm_dn = 2 * 128 * 256 + 2 * 64 * 256;   // 98304
    const int sm_up = 2 * 128 * 128 + 2 * 128 * 128;  // 65536
    cudaFuncSetAttribute(gemm_mma<HH, HH>, cudaFuncAttributeMaxDynamicSharedMemorySize, sm_hh);
    cudaFuncSetAttribute(gemm_mma<HH, IC>, cudaFuncAttributeMaxDynamicSharedMemorySize, sm_dn);
    cudaFuncSetAttribute(gemm_mma<IC, HH>, cudaFuncAttributeMaxDynamicSharedMemorySize, sm_up);

    const int gblocks = (E + 127) / 128;
    #define SLOT_HI(s) (whi + (size_t)(s) * WS)
    #define SLOT_LO(s) (wlo + (size_t)(s) * WS)

    // rbf basis paths
    rb8_kernel<<<(E + 255) / 256, 256>>>(rbf, W_rbf1, rb8, E);
    rbfh_kernel<<<(E + 31) / 32, HH>>>(rb8, rbf, W_rbf2, W_rbf, rbfh, rbfh2, E);

    // x_ji = silu(e1 @ W_ji + b_ji)
    gemm_mma<HH, HH><<<gblocks, 256, sm_hh>>>(e1, SLOT_HI(0), SLOT_LO(0), b_ji, nullptr, nullptr, xji, nullptr, nullptr, E, 1);
    // A = silu(e1 @ W_kj + b_kj) * rbfh
    gemm_mma<HH, HH><<<gblocks, 256, sm_hh>>>(e1, SLOT_HI(1), SLOT_LO(1), b_kj, rbfh, nullptr, A, nullptr, nullptr, E, 1);
    // xdown = silu(A @ W_down)
    gemm_mma<HH, IC><<<gblocks, 256, sm_dn>>>(A, SLOT_HI(2), SLOT_LO(2), nullptr, nullptr, nullptr, xdown, nullptr, nullptr, E, 1);

    // zero accumulator
    zero4_kernel<<<(E * IC / 4 + 255) / 256, 256>>>((float4*)acc, E * IC / 4);

    // T-space projections
    proj8_kernel<TK, 320><<<2048, 256>>>(tt, W_t1, t8, T);
    proj8_kernel<SBFK, 64><<<2048, 256>>>(sbf, W_sbf1, s8, T);

    // gather * sbf_h * t_h, scatter-add by idx_ji
    triplet_kernel<<<2368, 256>>>(t8, s8, W_t2, W_sbf2, xdown, idx_kj, idx_ji, acc, T);

    // A = silu(acc @ W_up) + x_ji
    gemm_mma<IC, HH><<<gblocks, 256, sm_up>>>(acc, SLOT_HI(3), SLOT_LO(3), nullptr, nullptr, xji, A, nullptr, nullptr, E, 1);

    // residual before (1 layer)
    gemm_mma<HH, HH><<<gblocks, 256, sm_hh>>>(A, SLOT_HI(4), SLOT_LO(4), bb1, nullptr, nullptr, B, nullptr, nullptr, E, 1);
    gemm_mma<HH, HH><<<gblocks, 256, sm_hh>>>(B, SLOT_HI(5), SLOT_LO(5), bb2, nullptr, A, C, nullptr, nullptr, E, 1);

    // h = silu(C @ W_lin + b_lin) + e1
    gemm_mma<HH, HH><<<gblocks, 256, sm_hh>>>(C, SLOT_HI(6), SLOT_LO(6), b_lin, nullptr, e1, A, nullptr, nullptr, E, 1);

    // residual after layer 0
    gemm_mma<HH, HH><<<gblocks, 256, sm_hh>>>(A, SLOT_HI(7), SLOT_LO(7), ba1, nullptr, nullptr, B, nullptr, nullptr, E, 1);
    gemm_mma<HH, HH><<<gblocks, 256, sm_hh>>>(B, SLOT_HI(8), SLOT_LO(8), ba2, nullptr, A, C, nullptr, nullptr, E, 1);
    // residual after layer 1 -> final outputs (e1_out, e2_out = e1_out * rbfh2)
    gemm_mma<HH, HH><<<gblocks, 256, sm_hh>>>(C, SLOT_HI(9), SLOT_LO(9), ba1 + HH, nullptr, nullptr, B, nullptr, nullptr, E, 1);
    gemm_mma<HH, HH><<<gblocks, 256, sm_hh>>>(B, SLOT_HI(10), SLOT_LO(10), ba2 + HH, nullptr, C, out_e1, rbfh2, out_e2, E, 1);
}